// round 1
// baseline (speedup 1.0000x reference)
#include <cuda_runtime.h>

#define PATCH 32
#define MAXP  65536
#define NREAL 3

// Scratch (no allocations allowed)
__device__ float g_w[MAXP * 2];      // top-2 softmax scores per patch
__device__ int   g_meta[MAXP];       // i0 | i1<<8 | lvl<<16
__device__ int   g_start[MAXP];      // exclusive scan of counts
__device__ int   g_bsum[256];        // block sums -> block offsets

// ---------------------------------------------------------------------------
// Kernel 1: gate. One warp per patch: 4 dot products via shfl butterfly,
// softmax over 4 logits, top-2 selection, split level.
// ---------------------------------------------------------------------------
__global__ void gate_kernel(const float* __restrict__ x,
                            const float* __restrict__ Wg, int P) {
    int gw   = (blockIdx.x * blockDim.x + threadIdx.x) >> 5;
    int lane = threadIdx.x & 31;
    if (gw >= P) return;
    float xv = x[(long)gw * PATCH + lane];
    float d0 = xv * Wg[0 * PATCH + lane];
    float d1 = xv * Wg[1 * PATCH + lane];
    float d2 = xv * Wg[2 * PATCH + lane];
    float d3 = xv * Wg[3 * PATCH + lane];
#pragma unroll
    for (int off = 16; off; off >>= 1) {
        d0 += __shfl_xor_sync(0xffffffffu, d0, off);
        d1 += __shfl_xor_sync(0xffffffffu, d1, off);
        d2 += __shfl_xor_sync(0xffffffffu, d2, off);
        d3 += __shfl_xor_sync(0xffffffffu, d3, off);
    }
    if (lane == 0) {
        float l[4] = {d0, d1, d2, d3};
        float m = fmaxf(fmaxf(l[0], l[1]), fmaxf(l[2], l[3]));
        float e[4];
        float s = 0.f;
#pragma unroll
        for (int i = 0; i < 4; i++) { e[i] = expf(l[i] - m); s += e[i]; }
        float inv = 1.f / s;
        float sc[4];
#pragma unroll
        for (int i = 0; i < 4; i++) sc[i] = e[i] * inv;
        // top-2 (strict >, so ties keep lower index first — matches argsort(-s))
        int i0 = 0;
#pragma unroll
        for (int i = 1; i < 4; i++) if (sc[i] > sc[i0]) i0 = i;
        int i1 = -1;
#pragma unroll
        for (int i = 0; i < 4; i++)
            if (i != i0 && (i1 < 0 || sc[i] > sc[i1])) i1 = i;
        int lvl = -1;
        if (i0 < NREAL) lvl = max(lvl, i0);
        if (i1 < NREAL) lvl = max(lvl, i1);
        lvl = max(lvl, 0);
        g_w[gw * 2 + 0] = sc[i0];
        g_w[gw * 2 + 1] = sc[i1];
        g_meta[gw] = i0 | (i1 << 8) | (lvl << 16);
    }
}

// ---------------------------------------------------------------------------
// Kernel 2: per-block (256 patches) count sums
// ---------------------------------------------------------------------------
__global__ void bsum_kernel(int P) {
    __shared__ int s[256];
    int t = threadIdx.x;
    int p = blockIdx.x * 256 + t;
    int cnt = (p < P) ? (1 << ((g_meta[p] >> 16) & 3)) : 0;
    s[t] = cnt;
    __syncthreads();
#pragma unroll
    for (int off = 128; off; off >>= 1) {
        if (t < off) s[t] += s[t + off];
        __syncthreads();
    }
    if (t == 0) g_bsum[blockIdx.x] = s[0];
}

// ---------------------------------------------------------------------------
// Kernel 3: single-block exclusive scan of block sums (NB <= 256)
// ---------------------------------------------------------------------------
__global__ void scanb_kernel(int NB) {
    __shared__ int s[256];
    int t = threadIdx.x;
    int v = (t < NB) ? g_bsum[t] : 0;
    s[t] = v;
    __syncthreads();
#pragma unroll
    for (int off = 1; off < 256; off <<= 1) {
        int add = (t >= off) ? s[t - off] : 0;
        __syncthreads();
        s[t] += add;
        __syncthreads();
    }
    if (t < NB) g_bsum[t] = s[t] - v;  // exclusive
}

// ---------------------------------------------------------------------------
// Kernel 4: per-patch starts = within-block exclusive scan + block offset
// ---------------------------------------------------------------------------
__global__ void starts_kernel(int P) {
    __shared__ int s[256];
    int t = threadIdx.x;
    int p = blockIdx.x * 256 + t;
    int cnt = (p < P) ? (1 << ((g_meta[p] >> 16) & 3)) : 0;
    s[t] = cnt;
    __syncthreads();
#pragma unroll
    for (int off = 1; off < 256; off <<= 1) {
        int add = (t >= off) ? s[t - off] : 0;
        __syncthreads();
        s[t] += add;
        __syncthreads();
    }
    if (p < P) g_start[p] = (s[t] - cnt) + g_bsum[blockIdx.x];
}

// ---------------------------------------------------------------------------
// Kernel 5: writer. One block per patch, 128 threads.
// Output layout (floats, concatenated flattened tensors):
//   [0,            32T)  new_x        [T,32]
//   [32T,          64T)  new_mask     [T,32]
//   [64T,          65T)  new_size     [T]
//   [65T,          67T)  weights      [T,2]
//   [67T,          69T)  expert_idx   [T,2]
//   [69T,         165T)  x_final      [T,3,32]
// ---------------------------------------------------------------------------
__global__ void write_kernel(const float* __restrict__ x,
                             const float* __restrict__ mask,
                             float* __restrict__ out, int P, int T) {
    int p = blockIdx.x;
    __shared__ float xs[32], ms[32];
    int tid = threadIdx.x;
    if (tid < 32) {
        xs[tid] = x[(long)p * 32 + tid];
        ms[tid] = mask[(long)p * 32 + tid];
    }
    __syncthreads();

    int meta = g_meta[p];
    int i0 = meta & 255, i1 = (meta >> 8) & 255, lvl = (meta >> 16) & 3;
    int start = g_start[p];
    int cnt = 1 << lvl;
    int sz  = 32 >> lvl;
    float w0 = g_w[p * 2], w1 = g_w[p * 2 + 1];

    long off_mask = (long)T * 32;
    long off_size = (long)T * 64;
    long off_w    = (long)T * 65;
    long off_e    = (long)T * 67;
    long off_f    = (long)T * 69;

    // new_x / new_mask: cnt*32 <= 128 elements
    if (tid < cnt * 32) {
        int c = tid >> 5, j = tid & 31;
        float vx = (j < sz) ? xs[c * sz + j] : 0.f;
        float vm = (j < sz) ? ms[c * sz + j] : 0.f;
        long o = (long)(start + c) * 32 + j;
        out[o] = vx;
        out[off_mask + o] = vm;
    }
    // new_size
    if (tid < cnt) out[off_size + start + tid] = (float)sz;
    // weights + expert ids
    if (tid < cnt * 2) {
        int c = tid >> 1, k = tid & 1;
        out[off_w + (long)(start + c) * 2 + k] = k ? w1 : w0;
        out[off_e + (long)(start + c) * 2 + k] = (float)(k ? i1 : i0);
    }
    // x_final: cnt*96 <= 384 elements
    for (int k = tid; k < cnt * 96; k += 128) {
        int c = k / 96, r = k % 96;
        int l = r >> 5, j = r & 31;
        bool on = (l == lvl) && (j >= c * sz) && (j < (c + 1) * sz);
        if (!on && lvl >= 1 && l == lvl - 1) {
            int szp = 64 >> lvl;  // 32 >> (lvl-1)
            int cp = c >> 1;
            on = (j >= cp * szp) && (j < (cp + 1) * szp);
        }
        out[off_f + (long)(start + c) * 96 + l * 32 + j] = on ? xs[j] * ms[j] : 0.f;
    }
}

// ---------------------------------------------------------------------------
extern "C" void kernel_launch(void* const* d_in, const int* in_sizes, int n_in,
                              void* d_out, int out_size) {
    const float* x    = (const float*)d_in[0];
    const float* mask = (const float*)d_in[1];
    const float* Wg   = (const float*)d_in[2];
    float* out = (float*)d_out;

    int n = in_sizes[0];
    int P = n / PATCH;                 // 65536
    int T = out_size / 165;            // reference total child count

    int gate_blocks = (P + 7) / 8;     // 8 warps per 256-thread block
    gate_kernel<<<gate_blocks, 256>>>(x, Wg, P);

    int NB = (P + 255) / 256;          // <= 256
    bsum_kernel<<<NB, 256>>>(P);
    scanb_kernel<<<1, 256>>>(NB);
    starts_kernel<<<NB, 256>>>(P);

    write_kernel<<<P, 128>>>(x, mask, out, P, T);
}

// round 2
// speedup vs baseline: 2.3031x; 2.3031x over previous
#include <cuda_runtime.h>

#define PATCH 32
#define MAXP  65536
#define NREAL 3

// Scratch (no allocations allowed)
__device__ float g_w[MAXP * 2];      // top-2 softmax scores per patch
__device__ int   g_meta[MAXP];       // i0 | i1<<8 | lvl<<16
__device__ int   g_start[MAXP];      // exclusive scan of counts
__device__ int   g_bsum[256];        // per-256-patch block sums -> offsets

// ---------------------------------------------------------------------------
// Kernel 1: gate + per-block count sum. One THREAD per patch (each thread owns
// exactly one 128B line of x -> L1-friendly). Dot reduction uses the same
// butterfly tree order as the previous (passing) shfl version so logits are
// bit-identical -> identical routing -> identical T.
// Block = 256 threads = 256 patches; writes g_bsum[blockIdx.x] directly.
// ---------------------------------------------------------------------------
__global__ void gate_kernel(const float4* __restrict__ x4,
                            const float* __restrict__ Wg, int P) {
    __shared__ float wg[4 * PATCH];
    __shared__ int wsum[8];
    int t = threadIdx.x;
    if (t < 128) wg[t] = Wg[t];
    __syncthreads();

    int p = blockIdx.x * 256 + t;
    int lvl = 0;
    if (p < P) {
        float xv[32];
#pragma unroll
        for (int q = 0; q < 8; q++) {
            float4 v = x4[(long)p * 8 + q];
            xv[q * 4 + 0] = v.x; xv[q * 4 + 1] = v.y;
            xv[q * 4 + 2] = v.z; xv[q * 4 + 3] = v.w;
        }
        float lgt[4];
#pragma unroll
        for (int e = 0; e < 4; e++) {
            float a[32];
#pragma unroll
            for (int j = 0; j < 32; j++) a[j] = xv[j] * wg[e * 32 + j];
            // butterfly tree order (matches shfl_xor 16,8,4,2,1 at lane 0)
#pragma unroll
            for (int off = 16; off >= 1; off >>= 1)
#pragma unroll
                for (int i = 0; i < off; i++) a[i] += a[i + off];
            lgt[e] = a[0];
        }
        float m = fmaxf(fmaxf(lgt[0], lgt[1]), fmaxf(lgt[2], lgt[3]));
        float e4[4], s = 0.f;
#pragma unroll
        for (int i = 0; i < 4; i++) { e4[i] = expf(lgt[i] - m); s += e4[i]; }
        float inv = 1.f / s;
        float sc[4];
#pragma unroll
        for (int i = 0; i < 4; i++) sc[i] = e4[i] * inv;
        int i0 = 0;
#pragma unroll
        for (int i = 1; i < 4; i++) if (sc[i] > sc[i0]) i0 = i;
        int i1 = -1;
#pragma unroll
        for (int i = 0; i < 4; i++)
            if (i != i0 && (i1 < 0 || sc[i] > sc[i1])) i1 = i;
        int lv = -1;
        if (i0 < NREAL) lv = max(lv, i0);
        if (i1 < NREAL) lv = max(lv, i1);
        lvl = max(lv, 0);
        g_w[p * 2 + 0] = sc[i0];
        g_w[p * 2 + 1] = sc[i1];
        g_meta[p] = i0 | (i1 << 8) | (lvl << 16);
    }
    // block-level count sum
    int cnt = (p < P) ? (1 << lvl) : 0;
    int ws = __reduce_add_sync(0xffffffffu, cnt);
    if ((t & 31) == 0) wsum[t >> 5] = ws;
    __syncthreads();
    if (t == 0) {
        int sum = 0;
#pragma unroll
        for (int i = 0; i < 8; i++) sum += wsum[i];
        g_bsum[blockIdx.x] = sum;
    }
}

// ---------------------------------------------------------------------------
// Kernel 2: exclusive scan of block sums (NB <= 256), shfl-based, 3 barriers.
// ---------------------------------------------------------------------------
__global__ void scanb_kernel(int NB) {
    __shared__ int ws[8];
    int t = threadIdx.x, lane = t & 31, wp = t >> 5;
    int v = (t < NB) ? g_bsum[t] : 0;
    int inc = v;
#pragma unroll
    for (int o = 1; o < 32; o <<= 1) {
        int u = __shfl_up_sync(0xffffffffu, inc, o);
        if (lane >= o) inc += u;
    }
    if (lane == 31) ws[wp] = inc;
    __syncthreads();
    if (wp == 0) {
        int s = (lane < 8) ? ws[lane] : 0;
#pragma unroll
        for (int o = 1; o < 8; o <<= 1) {
            int u = __shfl_up_sync(0xffffffffu, s, o);
            if (lane >= o) s += u;
        }
        if (lane < 8) ws[lane] = s;
    }
    __syncthreads();
    int off = wp ? ws[wp - 1] : 0;
    if (t < NB) g_bsum[t] = off + inc - v;   // exclusive
}

// ---------------------------------------------------------------------------
// Kernel 3: per-patch starts = within-block shfl scan + block offset.
// ---------------------------------------------------------------------------
__global__ void starts_kernel(int P) {
    __shared__ int ws[8];
    int t = threadIdx.x, lane = t & 31, wp = t >> 5;
    int p = blockIdx.x * 256 + t;
    int cnt = (p < P) ? (1 << ((g_meta[p] >> 16) & 3)) : 0;
    int inc = cnt;
#pragma unroll
    for (int o = 1; o < 32; o <<= 1) {
        int u = __shfl_up_sync(0xffffffffu, inc, o);
        if (lane >= o) inc += u;
    }
    if (lane == 31) ws[wp] = inc;
    __syncthreads();
    if (wp == 0) {
        int s = (lane < 8) ? ws[lane] : 0;
#pragma unroll
        for (int o = 1; o < 8; o <<= 1) {
            int u = __shfl_up_sync(0xffffffffu, s, o);
            if (lane >= o) s += u;
        }
        if (lane < 8) ws[lane] = s;
    }
    __syncthreads();
    int off = wp ? ws[wp - 1] : 0;
    if (p < P) g_start[p] = g_bsum[blockIdx.x] + off + inc - cnt;
}

// ---------------------------------------------------------------------------
// Kernel 4: writer. ONE WARP per patch, no smem. Lane j holds x[j], m[j] in
// registers; child gathers via shfl. All bulk stores are full-warp 128B
// aligned coalesced.
// Output layout (floats):
//   [0,32T) new_x   [32T,64T) new_mask  [64T,65T) new_size
//   [65T,67T) weights  [67T,69T) expert_idx  [69T,165T) x_final [T,3,32]
// ---------------------------------------------------------------------------
__global__ void write_kernel(const float* __restrict__ x,
                             const float* __restrict__ mask,
                             float* __restrict__ out, int P, long T) {
    int w = (blockIdx.x * blockDim.x + threadIdx.x) >> 5;
    int lane = threadIdx.x & 31;
    if (w >= P) return;

    float xv = x[(long)w * 32 + lane];
    float mv = mask[(long)w * 32 + lane];
    int meta  = g_meta[w];
    int start = g_start[w];
    float w0 = g_w[w * 2], w1 = g_w[w * 2 + 1];
    int i0 = meta & 255, i1 = (meta >> 8) & 255, lvl = (meta >> 16) & 3;
    int cnt = 1 << lvl, sz = 32 >> lvl;

    long offm = T * 32, offs = T * 64, offw = T * 65, offe = T * 67, offf = T * 69;
    float pm = xv * mv;

#pragma unroll
    for (int c = 0; c < 4; c++) {
        if (c >= cnt) break;
        int src = (c * sz + lane) & 31;
        float vx = __shfl_sync(0xffffffffu, xv, src);
        float vm = __shfl_sync(0xffffffffu, mv, src);
        bool val = lane < sz;
        long o = (long)(start + c) * 32 + lane;
        out[o]        = val ? vx : 0.f;
        out[offm + o] = val ? vm : 0.f;
        // x_final: 3 levels, 128B coalesced each
#pragma unroll
        for (int l = 0; l < 3; l++) {
            bool on = false;
            if (l == lvl) {
                on = (lane >= c * sz) && (lane < (c + 1) * sz);
            } else if (lvl >= 1 && l == lvl - 1) {
                int szp = sz * 2, cp = c >> 1;
                on = (lane >= cp * szp) && (lane < (cp + 1) * szp);
            }
            out[offf + (long)(start + c) * 96 + l * 32 + lane] = on ? pm : 0.f;
        }
    }
    if (lane < cnt) out[offs + start + lane] = (float)sz;
    if (lane < cnt * 2) {
        int c = lane >> 1, k = lane & 1;
        out[offw + (long)(start + c) * 2 + k] = k ? w1 : w0;
        out[offe + (long)(start + c) * 2 + k] = (float)(k ? i1 : i0);
    }
}

// ---------------------------------------------------------------------------
extern "C" void kernel_launch(void* const* d_in, const int* in_sizes, int n_in,
                              void* d_out, int out_size) {
    const float* x    = (const float*)d_in[0];
    const float* mask = (const float*)d_in[1];
    const float* Wg   = (const float*)d_in[2];
    float* out = (float*)d_out;

    int n = in_sizes[0];
    int P = n / PATCH;                 // 65536
    long T = out_size / 165;           // reference total child count

    int NB = (P + 255) / 256;          // 256
    gate_kernel<<<NB, 256>>>((const float4*)x, Wg, P);
    scanb_kernel<<<1, 256>>>(NB);
    starts_kernel<<<NB, 256>>>(P);
    write_kernel<<<(P * 32 + 255) / 256, 256>>>(x, mask, out, P, T);
}